// round 9
// baseline (speedup 1.0000x reference)
#include <cuda_runtime.h>
#include <cuda.h>
#include <math.h>
#include <stdint.h>

// ---------------- problem constants ----------------
#define NT      16384
#define DIM     2048
#define NE      64
#define TOPK    8
#define TILE_M  64
#define KC      64
#define NCHUNK  (DIM / KC)     // 32
#define THREADS 256

// ---------------- smem layout ----------------
#define XR_STAGE 16384          // raw x tile: 64 tok x 64 k fp32, rows 256B (x2 stages)
#define XD_STAGE 32768          // dup x tile: 64 tok x 64 slots x 8B (SINGLE buffer)
#define W_STAGE  16384          // wT tile: 64 k x 64 e fp32, rows 256B (x2 stages)
#define OFF_MBAR 0
#define OFF_GB   64
#define OFF_XR   1024
#define OFF_XD   (OFF_XR + 2 * XR_STAGE)    // 33792
#define OFF_W    (OFF_XD + XD_STAGE)        // 66560
#define SMEM_TOTAL (OFF_W + 2 * W_STAGE)    // 99328
#define TX_BYTES (XR_STAGE + W_STAGE)
#define SCROW 68                            // even stride: v2-store alignment safe

// transposed router weights: g_wT[k][e] = w[e][k]
__device__ __align__(1024) float g_wT[DIM * NE];
__device__ int g_nflag;
__device__ int g_flags[8192];

// ---------------- helpers ----------------
__device__ __forceinline__ uint32_t smem_u32(const void* p) {
    uint32_t a;
    asm("{ .reg .u64 t; cvta.to.shared.u64 t, %1; cvt.u32.u64 %0, t; }" : "=r"(a) : "l"(p));
    return a;
}

#define MBAR_INIT(addr, cnt) \
    asm volatile("mbarrier.init.shared.b64 [%0], %1;" :: "r"(addr), "r"((uint32_t)(cnt)) : "memory")
#define MBAR_EXPECT_TX(addr, bytes) \
    asm volatile("mbarrier.arrive.expect_tx.shared.b64 _, [%0], %1;" :: "r"(addr), "r"((uint32_t)(bytes)) : "memory")

#define MBAR_WAIT(addr, parity) do {                                           \
    uint32_t _m = (addr); uint32_t _p = (parity); uint32_t _d;                 \
    asm volatile("{\n\t.reg .pred p;\n\t"                                      \
        "mbarrier.try_wait.parity.acquire.cta.shared::cta.b64 p, [%1], %2;\n\t"\
        "selp.b32 %0, 1, 0, p;\n\t}"                                           \
        : "=r"(_d) : "r"(_m), "r"(_p) : "memory");                             \
    if (!_d) {                                                                 \
        asm volatile("{\n\t.reg .pred P1;\n\t"                                 \
            "WL_%=:\n\t"                                                       \
            "mbarrier.try_wait.parity.acquire.cta.shared::cta.b64 P1, [%0], %1, 0x989680;\n\t" \
            "@P1 bra.uni WD_%=;\n\t"                                           \
            "bra.uni WL_%=;\n\t"                                               \
            "WD_%=:\n\t}" :: "r"(_m), "r"(_p) : "memory");                     \
    }                                                                          \
} while (0)

__device__ __forceinline__ void tma_2d(uint32_t dst, const CUtensorMap* map,
                                       int32_t cx, int32_t cy, uint32_t mbar) {
    asm volatile(
        "cp.async.bulk.tensor.2d.shared::cta.global.tile.mbarrier::complete_tx::bytes "
        "[%0], [%1, {%2, %3}], [%4];"
        :: "r"(dst), "l"(map), "r"(cx), "r"(cy), "r"(mbar) : "memory");
}

// packed dual-fp32 FMA: acc.{lo,hi} += a.{lo,hi} * b.{lo,hi}
#define FFMA2(acc, a, b) \
    asm("fma.rn.f32x2 %0, %1, %2, %0;" : "+l"(acc) : "l"(a), "l"(b))

#define LDS64_U64(v, addr) \
    asm volatile("ld.shared.b64 %0, [%1];" : "=l"(v) : "r"(addr))
#define LDSV2_U64(v0, v1, addr) \
    asm volatile("ld.shared.v2.u64 {%0, %1}, [%2];" : "=l"(v0), "=l"(v1) : "r"(addr))
#define LDS128_F4(v, addr) \
    asm volatile("ld.shared.v4.f32 {%0, %1, %2, %3}, [%4];" \
        : "=f"((v).x), "=f"((v).y), "=f"((v).z), "=f"((v).w) : "r"(addr))
#define STSV2_F32(addr, f0, f1) \
    asm volatile("st.shared.v2.f32 [%0], {%1, %2};" :: "r"(addr), "f"(f0), "f"(f1) : "memory")

// ---------------- prep: transpose w -> wT[k][e]; reset flags ----------------
__global__ void prep_kernel(const float* __restrict__ w) {
    int idx = blockIdx.x * 256 + threadIdx.x;   // 0 .. DIM*NE-1
    if (idx == 0) g_nflag = 0;
    int k = idx >> 6;
    int e = idx & 63;
    g_wT[idx] = w[e * DIM + k];                 // coalesced write
}

// ---------------- main gate kernel ----------------
__global__ __launch_bounds__(THREADS) void gate_kernel(
    const __grid_constant__ CUtensorMap tmx,
    const __grid_constant__ CUtensorMap tmw,
    const float* __restrict__ gate_b,
    float* __restrict__ out)
{
    extern __shared__ __align__(1024) char smem[];
    const uint32_t sb = smem_u32(smem);
    const int tid = threadIdx.x;
    const int lane = tid & 31;
    const int wid = tid >> 5;
    const int t0 = wid * 8;                 // 8 tokens per warp
    const int tok0 = blockIdx.x * TILE_M;

    if (tid == 0) {
        MBAR_INIT(sb + OFF_MBAR + 0, 1);
        MBAR_INIT(sb + OFF_MBAR + 8, 1);
    }
    if (tid < NE) ((float*)(smem + OFF_GB))[tid] = gate_b[tid];
    __syncthreads();

    if (tid == 0) {
#pragma unroll
        for (int s = 0; s < 2; s++) {
            MBAR_EXPECT_TX(sb + OFF_MBAR + s * 8, TX_BYTES);
            tma_2d(sb + OFF_XR + s * XR_STAGE, &tmx, s * KC, tok0, sb + OFF_MBAR + s * 8);
            tma_2d(sb + OFF_W + s * W_STAGE, &tmw, 0, s * KC, sb + OFF_MBAR + s * 8);
        }
    }

    // acc2[t] : f32x2 {logit[t][2*lane], logit[t][2*lane+1]}
    unsigned long long acc2[8];
#pragma unroll
    for (int t = 0; t < 8; t++) acc2[t] = 0ULL;

    const uint32_t bcol = (uint32_t)lane * 8;   // expert-pair byte offset in wT row

    for (int c = 0; c < NCHUNK; c++) {
        const int s = c & 1, ph = (c >> 1) & 1;
        MBAR_WAIT(sb + OFF_MBAR + s * 8, ph);

        // ---- converter: raw x -> duplicated pairs (single XD buffer) ----
        // slot(k) = (k&3)*16 + (k>>2); xd[t][slot] = {x[t][k], x[t][k]} (8B per slot)
        {
            const uint32_t xr = sb + OFF_XR + s * XR_STAGE;
            const uint32_t xd = sb + OFF_XD;
#pragma unroll
            for (int i = 0; i < 4; i++) {
                const int fidx = tid + i * THREADS;       // float4 index 0..1023
                const int tt = fidx >> 4;                 // token
                const int kq = fidx & 15;                 // k quarter
                float4 v;
                LDS128_F4(v, xr + (uint32_t)fidx * 16);
                const uint32_t base = xd + (uint32_t)tt * 512 + (uint32_t)kq * 8;
                STSV2_F32(base,        v.x, v.x);         // k = 4kq+0 -> slot kq
                STSV2_F32(base + 128,  v.y, v.y);         // k = 4kq+1 -> slot 16+kq
                STSV2_F32(base + 256,  v.z, v.z);         // k = 4kq+2 -> slot 32+kq
                STSV2_F32(base + 384,  v.w, v.w);         // k = 4kq+3 -> slot 48+kq
            }
        }
        __syncthreads();

        // ---- compute: 512 FFMA2 per warp per chunk ----
        {
            const uint32_t wb = sb + OFF_W + s * W_STAGE + bcol;
            const uint32_t xw = sb + OFF_XD + (uint32_t)t0 * 512;
#pragma unroll 4
            for (int u = 0; u < 32; u++) {
                // slots 2u,2u+1 hold k0=8*(u&7)+(u>>3) and k0+4 (both duplicated)
                const int k0 = 8 * (u & 7) + (u >> 3);
                unsigned long long b20, b21;
                LDS64_U64(b20, wb + (uint32_t)k0 * 256);
                LDS64_U64(b21, wb + (uint32_t)k0 * 256 + 1024);
#pragma unroll
                for (int t = 0; t < 8; t++) {
                    unsigned long long a0, a1;
                    LDSV2_U64(a0, a1, xw + (uint32_t)t * 512 + (uint32_t)u * 16);
                    FFMA2(acc2[t], a0, b20);
                    FFMA2(acc2[t], a1, b21);
                }
            }
        }
        __syncthreads();

        if (tid == 0 && c + 2 < NCHUNK) {
            MBAR_EXPECT_TX(sb + OFF_MBAR + s * 8, TX_BYTES);
            tma_2d(sb + OFF_XR + s * XR_STAGE, &tmx, (c + 2) * KC, tok0, sb + OFF_MBAR + s * 8);
            tma_2d(sb + OFF_W + s * W_STAGE, &tmw, 0, (c + 2) * KC, sb + OFF_MBAR + s * 8);
        }
    }

    // ---- epilogue: logits -> smem (alias xr stages), per-token sigmoid+top-8 ----
    float* sc = (float*)(smem + OFF_XR);   // [64 tok][SCROW]
#pragma unroll
    for (int t = 0; t < 8; t++) {
        float lo, hi;
        asm("mov.b64 {%0, %1}, %2;" : "=f"(lo), "=f"(hi) : "l"(acc2[t]));
        STSV2_F32(sb + OFF_XR + ((uint32_t)(t0 + t) * SCROW + (uint32_t)lane * 2) * 4, lo, hi);
    }
    __syncthreads();

    if (tid < TILE_M) {
        const long token = tok0 + tid;
        const float* gb = (const float*)(smem + OFF_GB);
        float s[NE];
#pragma unroll
        for (int e = 0; e < NE; e++)
            s[e] = 1.f / (1.f + expf(-sc[tid * SCROW + e])) + gb[e];

        float* so = out + 2L * NT * TOPK + token * NE;
#pragma unroll
        for (int i = 0; i < 16; i++)
            *(float4*)&so[4 * i] = make_float4(s[4 * i], s[4 * i + 1], s[4 * i + 2], s[4 * i + 3]);

        // top-8, strict > keeps lowest index on ties (matches jax top_k)
        unsigned m0 = 0, m1 = 0;
        float wk[TOPK];
        int ik[TOPK];
        float sum = 0.f;
#pragma unroll 1
        for (int k = 0; k < TOPK; k++) {
            float best = -1e30f;
            int bi = 0;
#pragma unroll
            for (int e = 0; e < NE; e++) {
                unsigned bit = (e < 32) ? (m0 >> e) : (m1 >> (e - 32));
                if (((bit & 1u) == 0u) && (s[e] > best)) { best = s[e]; bi = e; }
            }
            if (bi < 32) m0 |= (1u << bi); else m1 |= (1u << (bi - 32));
            wk[k] = best; ik[k] = bi; sum += best;
        }
        // near-tie detection (incl. rank-8/9 boundary) -> flag for exact refine
        float v9 = -1e30f;
#pragma unroll
        for (int e = 0; e < NE; e++) {
            unsigned bit = (e < 32) ? (m0 >> e) : (m1 >> (e - 32));
            if (((bit & 1u) == 0u) && (s[e] > v9)) v9 = s[e];
        }
        float mingap = wk[TOPK - 1] - v9;
#pragma unroll
        for (int k = 0; k < TOPK - 1; k++) {
            float gdiff = wk[k] - wk[k + 1];
            if (gdiff < mingap) mingap = gdiff;
        }
        if (mingap < 2e-5f) {
            int ix = atomicAdd(&g_nflag, 1);
            if (ix < 8192) g_flags[ix] = (int)token;
        }

        float inv = 1.f / sum;
        *(float4*)&out[token * TOPK] = make_float4(wk[0] * inv, wk[1] * inv, wk[2] * inv, wk[3] * inv);
        *(float4*)&out[token * TOPK + 4] = make_float4(wk[4] * inv, wk[5] * inv, wk[6] * inv, wk[7] * inv);
        *(float4*)&out[NT * TOPK + token * TOPK] = make_float4((float)ik[0], (float)ik[1], (float)ik[2], (float)ik[3]);
        *(float4*)&out[NT * TOPK + token * TOPK + 4] = make_float4((float)ik[4], (float)ik[5], (float)ik[6], (float)ik[7]);
    }
}

// ---------------- refine: exact fp32 recompute for near-tie tokens ----------------
__global__ void refine_kernel(const float* __restrict__ x,
                              const float* __restrict__ w,
                              const float* __restrict__ gate_b,
                              float* __restrict__ out)
{
    __shared__ float xs[DIM];
    __shared__ float part[NE][4];
    __shared__ float sc[NE];
    int n = g_nflag;
    if (n > 8192) n = 8192;
    for (int i = blockIdx.x; i < n; i += gridDim.x) {
        const int token = g_flags[i];
        __syncthreads();
        for (int d = threadIdx.x; d < DIM; d += 256) xs[d] = x[(long)token * DIM + d];
        __syncthreads();
        {
            const int e = threadIdx.x >> 2, q = threadIdx.x & 3;
            const float* wr = w + (long)e * DIM + q * 512;
            const float* xr = xs + q * 512;
            float s0 = 0.f, s1 = 0.f, s2 = 0.f, s3 = 0.f;
#pragma unroll 8
            for (int d = 0; d < 512; d += 4) {
                s0 = fmaf(xr[d], wr[d], s0);
                s1 = fmaf(xr[d + 1], wr[d + 1], s1);
                s2 = fmaf(xr[d + 2], wr[d + 2], s2);
                s3 = fmaf(xr[d + 3], wr[d + 3], s3);
            }
            part[e][q] = (s0 + s1) + (s2 + s3);
        }
        __syncthreads();
        if (threadIdx.x < NE) {
            float l = (part[threadIdx.x][0] + part[threadIdx.x][1]) +
                      (part[threadIdx.x][2] + part[threadIdx.x][3]);
            float v = 1.f / (1.f + expf(-l)) + gate_b[threadIdx.x];
            sc[threadIdx.x] = v;
            out[2L * NT * TOPK + (long)token * NE + threadIdx.x] = v;
        }
        __syncthreads();
        if (threadIdx.x == 0) {
            unsigned m0 = 0, m1 = 0;
            float wk[TOPK];
            int ik[TOPK];
            float sum = 0.f;
            for (int k = 0; k < TOPK; k++) {
                float best = -1e30f;
                int bi = 0;
                for (int e = 0; e < NE; e++) {
                    unsigned bit = (e < 32) ? (m0 >> e) : (m1 >> (e - 32));
                    if (((bit & 1u) == 0u) && (sc[e] > best)) { best = sc[e]; bi = e; }
                }
                if (bi < 32) m0 |= (1u << bi); else m1 |= (1u << (bi - 32));
                wk[k] = best; ik[k] = bi; sum += best;
            }
            float inv = 1.f / sum;
            for (int k = 0; k < TOPK; k++) {
                out[(long)token * TOPK + k] = wk[k] * inv;
                out[NT * TOPK + (long)token * TOPK + k] = (float)ik[k];
            }
        }
    }
}

// ---------------- host ----------------
typedef CUresult (*EncodeFn)(CUtensorMap*, CUtensorMapDataType, cuuint32_t, void*,
                             const cuuint64_t*, const cuuint64_t*, const cuuint32_t*,
                             const cuuint32_t*, CUtensorMapInterleave, CUtensorMapSwizzle,
                             CUtensorMapL2promotion, CUtensorMapFloatOOBfill);

static EncodeFn get_encode_fn() {
    static EncodeFn fn = nullptr;
    if (!fn) {
        void* p = nullptr;
        cudaDriverEntryPointQueryResult qr;
        cudaGetDriverEntryPoint("cuTensorMapEncodeTiled", &p, cudaEnableDefault, &qr);
        fn = (EncodeFn)p;
    }
    return fn;
}

extern "C" void kernel_launch(void* const* d_in, const int* in_sizes, int n_in,
                              void* d_out, int out_size) {
    const float* x  = (const float*)d_in[0];
    const float* w  = (const float*)d_in[1];
    const float* gb = (const float*)d_in[2];
    float* out = (float*)d_out;

    prep_kernel<<<(DIM * NE) / 256, 256>>>(w);

    void* wtp = nullptr;
    cudaGetSymbolAddress(&wtp, g_wT);

    EncodeFn enc = get_encode_fn();
    CUtensorMap tmx, tmw;
    {
        cuuint64_t dims[2]    = {DIM, NT};
        cuuint64_t strides[1] = {DIM * sizeof(float)};
        cuuint32_t box[2]     = {KC, TILE_M};
        cuuint32_t es[2]      = {1, 1};
        enc(&tmx, CU_TENSOR_MAP_DATA_TYPE_FLOAT32, 2, (void*)x,
            dims, strides, box, es,
            CU_TENSOR_MAP_INTERLEAVE_NONE, CU_TENSOR_MAP_SWIZZLE_NONE,
            CU_TENSOR_MAP_L2_PROMOTION_L2_128B, CU_TENSOR_MAP_FLOAT_OOB_FILL_NONE);
    }
    {
        cuuint64_t dims[2]    = {NE, DIM};          // wT: inner = experts (256B rows)
        cuuint64_t strides[1] = {NE * sizeof(float)};
        cuuint32_t box[2]     = {NE, KC};
        cuuint32_t es[2]      = {1, 1};
        enc(&tmw, CU_TENSOR_MAP_DATA_TYPE_FLOAT32, 2, wtp,
            dims, strides, box, es,
            CU_TENSOR_MAP_INTERLEAVE_NONE, CU_TENSOR_MAP_SWIZZLE_NONE,
            CU_TENSOR_MAP_L2_PROMOTION_L2_128B, CU_TENSOR_MAP_FLOAT_OOB_FILL_NONE);
    }

    cudaFuncSetAttribute(gate_kernel, cudaFuncAttributeMaxDynamicSharedMemorySize, SMEM_TOTAL);
    gate_kernel<<<NT / TILE_M, THREADS, SMEM_TOTAL>>>(tmx, tmw, gb, out);
    refine_kernel<<<64, 256>>>(x, w, gb, out);
}

// round 10
// speedup vs baseline: 1.0294x; 1.0294x over previous
#include <cuda_runtime.h>
#include <cuda.h>
#include <math.h>
#include <stdint.h>

// ---------------- problem constants ----------------
#define NT      16384
#define DIM     2048
#define NE      64
#define TOPK    8
#define TILE_M  64
#define KC      64
#define KSPLIT  4
#define KPER    (DIM / KSPLIT)   // 512
#define CCHUNK  (KPER / KC)      // 8
#define THREADS 128

// ---------------- smem layout (gate) ----------------
#define X_STAGE  16384           // 64 tok x 64 k fp32, rows 256B
#define W_STAGE  16384           // 64 k x 64 e fp32, rows 256B
#define OFF_MBAR 0
#define OFF_X    1024
#define OFF_W    (OFF_X + 2 * X_STAGE)      // 33792
#define SMEM_TOTAL (OFF_W + 2 * W_STAGE)    // 66560
#define TX_BYTES (X_STAGE + W_STAGE)

// transposed router weights: g_wT[k][e] = w[e][k]
__device__ __align__(1024) float g_wT[DIM * NE];
// K-split partial logits: g_part[ks][token][expert]
__device__ __align__(1024) float g_part[KSPLIT * NT * NE];
__device__ int g_nflag;
__device__ int g_flags[8192];

// ---------------- helpers ----------------
__device__ __forceinline__ uint32_t smem_u32(const void* p) {
    uint32_t a;
    asm("{ .reg .u64 t; cvta.to.shared.u64 t, %1; cvt.u32.u64 %0, t; }" : "=r"(a) : "l"(p));
    return a;
}

#define MBAR_INIT(addr, cnt) \
    asm volatile("mbarrier.init.shared.b64 [%0], %1;" :: "r"(addr), "r"((uint32_t)(cnt)) : "memory")
#define MBAR_EXPECT_TX(addr, bytes) \
    asm volatile("mbarrier.arrive.expect_tx.shared.b64 _, [%0], %1;" :: "r"(addr), "r"((uint32_t)(bytes)) : "memory")

#define MBAR_WAIT(addr, parity) do {                                           \
    uint32_t _m = (addr); uint32_t _p = (parity); uint32_t _d;                 \
    asm volatile("{\n\t.reg .pred p;\n\t"                                      \
        "mbarrier.try_wait.parity.acquire.cta.shared::cta.b64 p, [%1], %2;\n\t"\
        "selp.b32 %0, 1, 0, p;\n\t}"                                           \
        : "=r"(_d) : "r"(_m), "r"(_p) : "memory");                             \
    if (!_d) {                                                                 \
        asm volatile("{\n\t.reg .pred P1;\n\t"                                 \
            "WL_%=:\n\t"                                                       \
            "mbarrier.try_wait.parity.acquire.cta.shared::cta.b64 P1, [%0], %1, 0x989680;\n\t" \
            "@P1 bra.uni WD_%=;\n\t"                                           \
            "bra.uni WL_%=;\n\t"                                               \
            "WD_%=:\n\t}" :: "r"(_m), "r"(_p) : "memory");                     \
    }                                                                          \
} while (0)

__device__ __forceinline__ void tma_2d(uint32_t dst, const CUtensorMap* map,
                                       int32_t cx, int32_t cy, uint32_t mbar) {
    asm volatile(
        "cp.async.bulk.tensor.2d.shared::cta.global.tile.mbarrier::complete_tx::bytes "
        "[%0], [%1, {%2, %3}], [%4];"
        :: "r"(dst), "l"(map), "r"(cx), "r"(cy), "r"(mbar) : "memory");
}

#define LDS128_F4(v, addr) \
    asm volatile("ld.shared.v4.f32 {%0, %1, %2, %3}, [%4];" \
        : "=f"((v).x), "=f"((v).y), "=f"((v).z), "=f"((v).w) : "r"(addr))

__device__ __forceinline__ void fma4(float4& acc, float a, const float4& b) {
    acc.x = fmaf(a, b.x, acc.x);
    acc.y = fmaf(a, b.y, acc.y);
    acc.z = fmaf(a, b.z, acc.z);
    acc.w = fmaf(a, b.w, acc.w);
}

// ---------------- prep: transpose w -> wT[k][e]; reset flags ----------------
__global__ void prep_kernel(const float* __restrict__ w) {
    int idx = blockIdx.x * 256 + threadIdx.x;   // 0 .. DIM*NE-1
    if (idx == 0) g_nflag = 0;
    int k = idx >> 6;
    int e = idx & 63;
    g_wT[idx] = w[e * DIM + k];                 // coalesced write
}

// ---------------- gate: K-split partial GEMM (FFMA-bound) ----------------
__global__ __launch_bounds__(THREADS) void gate_kernel(
    const __grid_constant__ CUtensorMap tmx,
    const __grid_constant__ CUtensorMap tmw)
{
    extern __shared__ __align__(1024) char smem[];
    const uint32_t sb = smem_u32(smem);
    const int tid = threadIdx.x;
    const int tg = tid >> 3;        // 16 groups x 4 tokens
    const int eg = tid & 7;         // 8 groups x 8 experts
    const int tokTile = blockIdx.x >> 2;
    const int ks = blockIdx.x & 3;
    const int tok0 = tokTile * TILE_M;
    const int k0 = ks * KPER;

    if (tid == 0) {
        MBAR_INIT(sb + OFF_MBAR + 0, 1);
        MBAR_INIT(sb + OFF_MBAR + 8, 1);
    }
    __syncthreads();

    if (tid == 0) {
#pragma unroll
        for (int s = 0; s < 2; s++) {
            MBAR_EXPECT_TX(sb + OFF_MBAR + s * 8, TX_BYTES);
            tma_2d(sb + OFF_X + s * X_STAGE, &tmx, k0 + s * KC, tok0, sb + OFF_MBAR + s * 8);
            tma_2d(sb + OFF_W + s * W_STAGE, &tmw, 0, k0 + s * KC, sb + OFF_MBAR + s * 8);
        }
    }

    float4 acc[4][2];
#pragma unroll
    for (int i = 0; i < 4; i++) {
        acc[i][0] = make_float4(0.f, 0.f, 0.f, 0.f);
        acc[i][1] = make_float4(0.f, 0.f, 0.f, 0.f);
    }

    const uint32_t abase = (uint32_t)(tg * 4) * 256;   // 4 token rows
    const uint32_t bbase = (uint32_t)eg * 32;          // 8-expert byte offset

    for (int c = 0; c < CCHUNK; c++) {
        const int s = c & 1, ph = (c >> 1) & 1;
        MBAR_WAIT(sb + OFF_MBAR + s * 8, ph);

        const uint32_t xb = sb + OFF_X + s * X_STAGE + abase;
        const uint32_t wb = sb + OFF_W + s * W_STAGE + bbase;

#pragma unroll 2
        for (int kk = 0; kk < KC; kk += 4) {
            float4 a[4];
#pragma unroll
            for (int i = 0; i < 4; i++) LDS128_F4(a[i], xb + i * 256u + (uint32_t)kk * 4);
#pragma unroll
            for (int d = 0; d < 4; d++) {
                float4 b0, b1;
                LDS128_F4(b0, wb + (uint32_t)(kk + d) * 256);
                LDS128_F4(b1, wb + (uint32_t)(kk + d) * 256 + 16);
#pragma unroll
                for (int i = 0; i < 4; i++) {
                    const float as = (d == 0) ? a[i].x : (d == 1) ? a[i].y
                                   : (d == 2) ? a[i].z : a[i].w;
                    fma4(acc[i][0], as, b0);
                    fma4(acc[i][1], as, b1);
                }
            }
        }
        __syncthreads();

        if (tid == 0 && c + 2 < CCHUNK) {
            MBAR_EXPECT_TX(sb + OFF_MBAR + s * 8, TX_BYTES);
            tma_2d(sb + OFF_X + s * X_STAGE, &tmx, k0 + (c + 2) * KC, tok0, sb + OFF_MBAR + s * 8);
            tma_2d(sb + OFF_W + s * W_STAGE, &tmw, 0, k0 + (c + 2) * KC, sb + OFF_MBAR + s * 8);
        }
    }

    // write partial logits: g_part[ks][token][expert]
    float* pp = g_part + (long)ks * NT * NE;
#pragma unroll
    for (int i = 0; i < 4; i++) {
        const long token = tok0 + tg * 4 + i;
        *(float4*)&pp[token * NE + eg * 8] = acc[i][0];
        *(float4*)&pp[token * NE + eg * 8 + 4] = acc[i][1];
    }
}

// ---------------- topk: sum partials, sigmoid+bias, top-8, flags ----------------
__global__ __launch_bounds__(256) void topk_kernel(
    const float* __restrict__ gate_b,
    float* __restrict__ out)
{
    __shared__ float gb[NE];
    if (threadIdx.x < NE) gb[threadIdx.x] = gate_b[threadIdx.x];
    __syncthreads();

    const long token = blockIdx.x * 256 + threadIdx.x;
    const float* p0 = g_part + token * NE;
    const float* p1 = p0 + (long)NT * NE;
    const float* p2 = p1 + (long)NT * NE;
    const float* p3 = p2 + (long)NT * NE;

    float s[NE];
#pragma unroll
    for (int q = 0; q < 16; q++) {
        float4 v0 = *(const float4*)&p0[4 * q];
        float4 v1 = *(const float4*)&p1[4 * q];
        float4 v2 = *(const float4*)&p2[4 * q];
        float4 v3 = *(const float4*)&p3[4 * q];
        s[4 * q + 0] = (v0.x + v1.x) + (v2.x + v3.x);
        s[4 * q + 1] = (v0.y + v1.y) + (v2.y + v3.y);
        s[4 * q + 2] = (v0.z + v1.z) + (v2.z + v3.z);
        s[4 * q + 3] = (v0.w + v1.w) + (v2.w + v3.w);
    }
#pragma unroll
    for (int e = 0; e < NE; e++)
        s[e] = 1.f / (1.f + expf(-s[e])) + gb[e];

    float* so = out + 2L * NT * TOPK + token * NE;
#pragma unroll
    for (int q = 0; q < 16; q++)
        *(float4*)&so[4 * q] = make_float4(s[4 * q], s[4 * q + 1], s[4 * q + 2], s[4 * q + 3]);

    // top-8, strict > keeps lowest index on ties (matches jax top_k)
    unsigned m0 = 0, m1 = 0;
    float wk[TOPK];
    int ik[TOPK];
    float sum = 0.f;
#pragma unroll 1
    for (int k = 0; k < TOPK; k++) {
        float best = -1e30f;
        int bi = 0;
#pragma unroll
        for (int e = 0; e < NE; e++) {
            unsigned bit = (e < 32) ? (m0 >> e) : (m1 >> (e - 32));
            if (((bit & 1u) == 0u) && (s[e] > best)) { best = s[e]; bi = e; }
        }
        if (bi < 32) m0 |= (1u << bi); else m1 |= (1u << (bi - 32));
        wk[k] = best; ik[k] = bi; sum += best;
    }
    // near-tie detection (incl. rank-8/9 boundary) -> flag for exact refine
    float v9 = -1e30f;
#pragma unroll
    for (int e = 0; e < NE; e++) {
        unsigned bit = (e < 32) ? (m0 >> e) : (m1 >> (e - 32));
        if (((bit & 1u) == 0u) && (s[e] > v9)) v9 = s[e];
    }
    float mingap = wk[TOPK - 1] - v9;
#pragma unroll
    for (int k = 0; k < TOPK - 1; k++) {
        float gdiff = wk[k] - wk[k + 1];
        if (gdiff < mingap) mingap = gdiff;
    }
    if (mingap < 2e-5f) {
        int ix = atomicAdd(&g_nflag, 1);
        if (ix < 8192) g_flags[ix] = (int)token;
    }

    float inv = 1.f / sum;
    *(float4*)&out[token * TOPK] = make_float4(wk[0] * inv, wk[1] * inv, wk[2] * inv, wk[3] * inv);
    *(float4*)&out[token * TOPK + 4] = make_float4(wk[4] * inv, wk[5] * inv, wk[6] * inv, wk[7] * inv);
    *(float4*)&out[NT * TOPK + token * TOPK] = make_float4((float)ik[0], (float)ik[1], (float)ik[2], (float)ik[3]);
    *(float4*)&out[NT * TOPK + token * TOPK + 4] = make_float4((float)ik[4], (float)ik[5], (float)ik[6], (float)ik[7]);
}

// ---------------- refine: exact fp32 recompute for near-tie tokens ----------------
__global__ void refine_kernel(const float* __restrict__ x,
                              const float* __restrict__ w,
                              const float* __restrict__ gate_b,
                              float* __restrict__ out)
{
    __shared__ float xs[DIM];
    __shared__ float part[NE][4];
    __shared__ float sc[NE];
    int n = g_nflag;
    if (n > 8192) n = 8192;
    for (int i = blockIdx.x; i < n; i += gridDim.x) {
        const int token = g_flags[i];
        __syncthreads();
        for (int d = threadIdx.x; d < DIM; d += 256) xs[d] = x[(long)token * DIM + d];
        __syncthreads();
        {
            const int e = threadIdx.x >> 2, q = threadIdx.x & 3;
            const float* wr = w + (long)e * DIM + q * 512;
            const float* xr = xs + q * 512;
            float s0 = 0.f, s1 = 0.f, s2 = 0.f, s3 = 0.f;
#pragma unroll 8
            for (int d = 0; d < 512; d += 4) {
                s0 = fmaf(xr[d], wr[d], s0);
                s1 = fmaf(xr[d + 1], wr[d + 1], s1);
                s2 = fmaf(xr[d + 2], wr[d + 2], s2);
                s3 = fmaf(xr[d + 3], wr[d + 3], s3);
            }
            part[e][q] = (s0 + s1) + (s2 + s3);
        }
        __syncthreads();
        if (threadIdx.x < NE) {
            float l = (part[threadIdx.x][0] + part[threadIdx.x][1]) +
                      (part[threadIdx.x][2] + part[threadIdx.x][3]);
            float v = 1.f / (1.f + expf(-l)) + gate_b[threadIdx.x];
            sc[threadIdx.x] = v;
            out[2L * NT * TOPK + (long)token * NE + threadIdx.x] = v;
        }
        __syncthreads();
        if (threadIdx.x == 0) {
            unsigned m0 = 0, m1 = 0;
            float wk[TOPK];
            int ik[TOPK];
            float sum = 0.f;
            for (int k = 0; k < TOPK; k++) {
                float best = -1e30f;
                int bi = 0;
                for (int e = 0; e < NE; e++) {
                    unsigned bit = (e < 32) ? (m0 >> e) : (m1 >> (e - 32));
                    if (((bit & 1u) == 0u) && (sc[e] > best)) { best = sc[e]; bi = e; }
                }
                if (bi < 32) m0 |= (1u << bi); else m1 |= (1u << (bi - 32));
                wk[k] = best; ik[k] = bi; sum += best;
            }
            float inv = 1.f / sum;
            for (int k = 0; k < TOPK; k++) {
                out[(long)token * TOPK + k] = wk[k] * inv;
                out[NT * TOPK + (long)token * TOPK + k] = (float)ik[k];
            }
        }
    }
}

// ---------------- host ----------------
typedef CUresult (*EncodeFn)(CUtensorMap*, CUtensorMapDataType, cuuint32_t, void*,
                             const cuuint64_t*, const cuuint64_t*, const cuuint32_t*,
                             const cuuint32_t*, CUtensorMapInterleave, CUtensorMapSwizzle,
                             CUtensorMapL2promotion, CUtensorMapFloatOOBfill);

static EncodeFn get_encode_fn() {
    static EncodeFn fn = nullptr;
    if (!fn) {
        void* p = nullptr;
        cudaDriverEntryPointQueryResult qr;
        cudaGetDriverEntryPoint("cuTensorMapEncodeTiled", &p, cudaEnableDefault, &qr);
        fn = (EncodeFn)p;
    }
    return fn;
}

extern "C" void kernel_launch(void* const* d_in, const int* in_sizes, int n_in,
                              void* d_out, int out_size) {
    const float* x  = (const float*)d_in[0];
    const float* w  = (const float*)d_in[1];
    const float* gb = (const float*)d_in[2];
    float* out = (float*)d_out;

    prep_kernel<<<(DIM * NE) / 256, 256>>>(w);

    void* wtp = nullptr;
    cudaGetSymbolAddress(&wtp, g_wT);

    EncodeFn enc = get_encode_fn();
    CUtensorMap tmx, tmw;
    {
        cuuint64_t dims[2]    = {DIM, NT};
        cuuint64_t strides[1] = {DIM * sizeof(float)};
        cuuint32_t box[2]     = {KC, TILE_M};
        cuuint32_t es[2]      = {1, 1};
        enc(&tmx, CU_TENSOR_MAP_DATA_TYPE_FLOAT32, 2, (void*)x,
            dims, strides, box, es,
            CU_TENSOR_MAP_INTERLEAVE_NONE, CU_TENSOR_MAP_SWIZZLE_NONE,
            CU_TENSOR_MAP_L2_PROMOTION_L2_128B, CU_TENSOR_MAP_FLOAT_OOB_FILL_NONE);
    }
    {
        cuuint64_t dims[2]    = {NE, DIM};          // wT rows: 64 experts x 4B = 256B
        cuuint64_t strides[1] = {NE * sizeof(float)};
        cuuint32_t box[2]     = {NE, KC};
        cuuint32_t es[2]      = {1, 1};
        enc(&tmw, CU_TENSOR_MAP_DATA_TYPE_FLOAT32, 2, wtp,
            dims, strides, box, es,
            CU_TENSOR_MAP_INTERLEAVE_NONE, CU_TENSOR_MAP_SWIZZLE_NONE,
            CU_TENSOR_MAP_L2_PROMOTION_L2_128B, CU_TENSOR_MAP_FLOAT_OOB_FILL_NONE);
    }

    cudaFuncSetAttribute(gate_kernel, cudaFuncAttributeMaxDynamicSharedMemorySize, SMEM_TOTAL);
    gate_kernel<<<(NT / TILE_M) * KSPLIT, THREADS, SMEM_TOTAL>>>(tmx, tmw);
    topk_kernel<<<NT / 256, 256>>>(gb, out);
    refine_kernel<<<64, 256>>>(x, w, gb, out);
}

// round 11
// speedup vs baseline: 2.9703x; 2.8855x over previous
#include <cuda_runtime.h>
#include <cuda.h>
#include <cuda_fp16.h>
#include <math.h>
#include <stdint.h>

// ---------------- problem constants ----------------
#define NT      16384
#define DIM     2048
#define NE      64
#define TOPK    8
#define TILE_M  128
#define KC      64
#define NCHUNK  (DIM / KC)     // 32
#define THREADS 256

// ---------------- smem layout (dynamic, bytes) ----------------
#define X_STAGE  32768                         // 128 x 64 fp32
#define W_STAGE  16384                         // 128 rows x 64 fp16 (w0|w1 stacked)
#define XH_STAGE 16384                         // 128 x 64 fp16
#define OFF_MBAR 0
#define OFF_GB   64
#define OFF_X    1024
#define OFF_W    (OFF_X + 2 * X_STAGE)         // 66560
#define OFF_XH0  (OFF_W + 2 * W_STAGE)         // 99328
#define OFF_XH1  (OFF_XH0 + 2 * XH_STAGE)      // 132096
#define SMEM_TOTAL (OFF_XH1 + 2 * XH_STAGE)    // 164864
#define TX_BYTES (X_STAGE + W_STAGE)

// split router weights: rows 0..63 = h0(w[e]), rows 64..127 = h1 residual
__device__ __align__(1024) __half g_wh[2 * NE * DIM];
__device__ int g_nflag;
__device__ int g_flags[8192];

// ---------------- helpers ----------------
__device__ __forceinline__ uint32_t smem_u32(const void* p) {
    uint32_t a;
    asm("{ .reg .u64 t; cvta.to.shared.u64 t, %1; cvt.u32.u64 %0, t; }" : "=r"(a) : "l"(p));
    return a;
}

#define MBAR_INIT(addr, cnt) \
    asm volatile("mbarrier.init.shared.b64 [%0], %1;" :: "r"(addr), "r"((uint32_t)(cnt)) : "memory")
#define MBAR_EXPECT_TX(addr, bytes) \
    asm volatile("mbarrier.arrive.expect_tx.shared.b64 _, [%0], %1;" :: "r"(addr), "r"((uint32_t)(bytes)) : "memory")

#define MBAR_WAIT(addr, parity) do {                                           \
    uint32_t _m = (addr); uint32_t _p = (parity); uint32_t _d;                 \
    asm volatile("{\n\t.reg .pred p;\n\t"                                      \
        "mbarrier.try_wait.parity.acquire.cta.shared::cta.b64 p, [%1], %2;\n\t"\
        "selp.b32 %0, 1, 0, p;\n\t}"                                           \
        : "=r"(_d) : "r"(_m), "r"(_p) : "memory");                             \
    if (!_d) {                                                                 \
        asm volatile("{\n\t.reg .pred P1;\n\t"                                 \
            "WL_%=:\n\t"                                                       \
            "mbarrier.try_wait.parity.acquire.cta.shared::cta.b64 P1, [%0], %1, 0x989680;\n\t" \
            "@P1 bra.uni WD_%=;\n\t"                                           \
            "bra.uni WL_%=;\n\t"                                               \
            "WD_%=:\n\t}" :: "r"(_m), "r"(_p) : "memory");                     \
    }                                                                          \
} while (0)

__device__ __forceinline__ void tma_2d(uint32_t dst, const CUtensorMap* map,
                                       int32_t cx, int32_t cy, uint32_t mbar) {
    asm volatile(
        "cp.async.bulk.tensor.2d.shared::cta.global.tile.mbarrier::complete_tx::bytes "
        "[%0], [%1, {%2, %3}], [%4];"
        :: "r"(dst), "l"(map), "r"(cx), "r"(cy), "r"(mbar) : "memory");
}

#define LDSM4(r, addr)                                                         \
    asm volatile("ldmatrix.sync.aligned.m8n8.x4.shared.b16 {%0,%1,%2,%3}, [%4];" \
        : "=r"((r)[0]), "=r"((r)[1]), "=r"((r)[2]), "=r"((r)[3]) : "r"(addr))

#define MMA16816(c, a, b0, b1)                                                 \
    asm volatile("mma.sync.aligned.m16n8k16.row.col.f32.f16.f16.f32 "          \
        "{%0,%1,%2,%3}, {%4,%5,%6,%7}, {%8,%9}, {%0,%1,%2,%3};"                \
        : "+f"((c)[0]), "+f"((c)[1]), "+f"((c)[2]), "+f"((c)[3])               \
        : "r"((a)[0]), "r"((a)[1]), "r"((a)[2]), "r"((a)[3]), "r"(b0), "r"(b1))

// SW128: 16B group g in 128B row r -> g ^ (r&7)
__device__ __forceinline__ uint32_t SWZ(int r, int k) {
    return (uint32_t)(r * 128 + ((((k) >> 3) ^ (r & 7)) << 4));
}

// ---------------- prep: split w to fp16 pairs; reset flag count ----------------
__global__ void prep_kernel(const float* __restrict__ w) {
    int i = blockIdx.x * 256 + threadIdx.x;    // 0 .. NE*DIM-1
    if (i == 0) g_nflag = 0;
    float a = w[i];
    __half h0 = __float2half_rn(a);
    float r = a - __half2float(h0);
    __half h1 = __float2half_rn(r);
    int e = i >> 11, d = i & 2047;
    g_wh[e * DIM + d] = h0;
    g_wh[(NE + e) * DIM + d] = h1;
}

// ---------------- main gate kernel (fp16 3-term split via mma.sync) ----------------
__global__ __launch_bounds__(THREADS, 1) void gate_kernel(
    const __grid_constant__ CUtensorMap tmx,
    const __grid_constant__ CUtensorMap tmw,
    const float* __restrict__ gate_b,
    float* __restrict__ out)
{
    extern __shared__ __align__(1024) char smem[];
    const uint32_t sb = smem_u32(smem);
    const int tid = threadIdx.x;
    const int lane = tid & 31;
    const int wid = tid >> 5;
    const int tok0 = blockIdx.x * TILE_M;

    if (tid == 0) {
        MBAR_INIT(sb + OFF_MBAR + 0, 1);
        MBAR_INIT(sb + OFF_MBAR + 8, 1);
    }
    if (tid < NE) ((float*)(smem + OFF_GB))[tid] = gate_b[tid];
    __syncthreads();

    if (tid == 0) {
#pragma unroll
        for (int c = 0; c < 2; c++) {
            MBAR_EXPECT_TX(sb + OFF_MBAR + c * 8, TX_BYTES);
            tma_2d(sb + OFF_X + c * X_STAGE, &tmx, c * KC, tok0, sb + OFF_MBAR + c * 8);
            tma_2d(sb + OFF_W + c * W_STAGE, &tmw, c * KC, 0, sb + OFF_MBAR + c * 8);
        }
    }

    float acc[2][4][4];
#pragma unroll
    for (int mt = 0; mt < 2; mt++)
#pragma unroll
        for (int nt = 0; nt < 4; nt++)
#pragma unroll
            for (int j = 0; j < 4; j++) acc[mt][nt][j] = 0.f;

    const int wm = wid & 3, wn = wid >> 2;
    const int tm0 = wm * 32, en0 = wn * 32;
    const int ar = (lane & 7) + ((lane & 8) ? 8 : 0);
    const int ak = (lane & 16) ? 8 : 0;
    const int br = (lane & 7) + ((lane & 16) ? 8 : 0);
    const int bk = (lane & 8) ? 8 : 0;

    for (int c = 0; c < NCHUNK; c++) {
        const int s = c & 1, ph = (c >> 1) & 1;
        MBAR_WAIT(sb + OFF_MBAR + s * 8, ph);

        // ---- convert x fp32 -> (h0, h1) fp16 tiles with SW128 ----
        {
            const char* xsrc = smem + OFF_X + s * X_STAGE;
            char* d0 = smem + OFF_XH0 + s * XH_STAGE;
            char* d1 = smem + OFF_XH1 + s * XH_STAGE;
#pragma unroll
            for (int i = 0; i < 16; i++) {
                int p = tid + i * THREADS;                 // pair index 0..4095
                float2 v = *(const float2*)(xsrc + p * 8);
                __half2 h0 = __float22half2_rn(v);
                float2 bl = __half22float2(h0);
                __half2 h1 = __float22half2_rn(make_float2(v.x - bl.x, v.y - bl.y));
                int row = p >> 5, pc = p & 31;
                uint32_t off = (uint32_t)(row * 128 + ((((pc >> 2)) ^ (row & 7)) << 4) + (pc & 3) * 4);
                *(__half2*)(d0 + off) = h0;
                *(__half2*)(d1 + off) = h1;
            }
        }
        __syncthreads();

        // ---- MMA: 3 terms (x0w0, x0w1, x1w0) over this K=64 chunk ----
        {
            const uint32_t xh0b = sb + OFF_XH0 + s * XH_STAGE;
            const uint32_t xh1b = sb + OFF_XH1 + s * XH_STAGE;
            const uint32_t wb = sb + OFF_W + s * W_STAGE;
#pragma unroll
            for (int ks = 0; ks < 4; ks++) {
                const int kk = ks * 16;
                uint32_t a00[4], a01[4], a10[4], a11[4];
                LDSM4(a00, xh0b + SWZ(tm0 + ar, kk + ak));
                LDSM4(a01, xh0b + SWZ(tm0 + 16 + ar, kk + ak));
                LDSM4(a10, xh1b + SWZ(tm0 + ar, kk + ak));
                LDSM4(a11, xh1b + SWZ(tm0 + 16 + ar, kk + ak));
                uint32_t b0[8], b1[8];
                LDSM4(b0 + 0, wb + SWZ(en0 + br, kk + bk));
                LDSM4(b0 + 4, wb + SWZ(en0 + 16 + br, kk + bk));
                LDSM4(b1 + 0, wb + SWZ(64 + en0 + br, kk + bk));
                LDSM4(b1 + 4, wb + SWZ(64 + en0 + 16 + br, kk + bk));
#pragma unroll
                for (int nt = 0; nt < 4; nt++) {
                    MMA16816(acc[0][nt], a00, b0[2 * nt], b0[2 * nt + 1]);
                    MMA16816(acc[1][nt], a01, b0[2 * nt], b0[2 * nt + 1]);
                    MMA16816(acc[0][nt], a00, b1[2 * nt], b1[2 * nt + 1]);
                    MMA16816(acc[1][nt], a01, b1[2 * nt], b1[2 * nt + 1]);
                    MMA16816(acc[0][nt], a10, b0[2 * nt], b0[2 * nt + 1]);
                    MMA16816(acc[1][nt], a11, b0[2 * nt], b0[2 * nt + 1]);
                }
            }
        }
        __syncthreads();

        if (tid == 0 && c + 2 < NCHUNK) {
            MBAR_EXPECT_TX(sb + OFF_MBAR + s * 8, TX_BYTES);
            tma_2d(sb + OFF_X + s * X_STAGE, &tmx, (c + 2) * KC, tok0, sb + OFF_MBAR + s * 8);
            tma_2d(sb + OFF_W + s * W_STAGE, &tmw, (c + 2) * KC, 0, sb + OFF_MBAR + s * 8);
        }
    }

    // ---- epilogue: logits -> smem, then per-token sigmoid + top-8 ----
    float* sc = (float*)(smem + OFF_X);   // [128][68]
    {
        const int g = lane >> 2, q = lane & 3;
#pragma unroll
        for (int mt = 0; mt < 2; mt++)
#pragma unroll
            for (int nt = 0; nt < 4; nt++) {
                int t0 = tm0 + mt * 16 + g;
                int e0 = en0 + nt * 8 + q * 2;
                sc[t0 * 68 + e0] = acc[mt][nt][0];
                sc[t0 * 68 + e0 + 1] = acc[mt][nt][1];
                sc[(t0 + 8) * 68 + e0] = acc[mt][nt][2];
                sc[(t0 + 8) * 68 + e0 + 1] = acc[mt][nt][3];
            }
    }
    __syncthreads();

    if (tid < TILE_M) {
        const long token = tok0 + tid;
        const float* gb = (const float*)(smem + OFF_GB);
        float s[NE];
#pragma unroll
        for (int e = 0; e < NE; e++)
            s[e] = 1.f / (1.f + expf(-sc[tid * 68 + e])) + gb[e];

        float* so = out + 2L * NT * TOPK + token * NE;
#pragma unroll
        for (int i = 0; i < 16; i++)
            *(float4*)&so[4 * i] = make_float4(s[4 * i], s[4 * i + 1], s[4 * i + 2], s[4 * i + 3]);

        // top-8, strict > keeps lowest index on ties
        unsigned m0 = 0, m1 = 0;
        float wk[TOPK];
        int ik[TOPK];
        float sum = 0.f;
#pragma unroll 1
        for (int k = 0; k < TOPK; k++) {
            float best = -1e30f;
            int bi = 0;
#pragma unroll
            for (int e = 0; e < NE; e++) {
                unsigned bit = (e < 32) ? (m0 >> e) : (m1 >> (e - 32));
                if (((bit & 1u) == 0u) && (s[e] > best)) { best = s[e]; bi = e; }
            }
            if (bi < 32) m0 |= (1u << bi); else m1 |= (1u << (bi - 32));
            wk[k] = best; ik[k] = bi; sum += best;
        }
        // near-tie detection (threshold 4e-6: >10x the measured 3-term error)
        float v9 = -1e30f;
#pragma unroll
        for (int e = 0; e < NE; e++) {
            unsigned bit = (e < 32) ? (m0 >> e) : (m1 >> (e - 32));
            if (((bit & 1u) == 0u) && (s[e] > v9)) v9 = s[e];
        }
        float mingap = wk[TOPK - 1] - v9;
#pragma unroll
        for (int k = 0; k < TOPK - 1; k++) {
            float gdiff = wk[k] - wk[k + 1];
            if (gdiff < mingap) mingap = gdiff;
        }
        if (mingap < 4e-6f) {
            int ix = atomicAdd(&g_nflag, 1);
            if (ix < 8192) g_flags[ix] = (int)token;
        }

        float inv = 1.f / sum;
        *(float4*)&out[token * TOPK] = make_float4(wk[0] * inv, wk[1] * inv, wk[2] * inv, wk[3] * inv);
        *(float4*)&out[token * TOPK + 4] = make_float4(wk[4] * inv, wk[5] * inv, wk[6] * inv, wk[7] * inv);
        *(float4*)&out[NT * TOPK + token * TOPK] = make_float4((float)ik[0], (float)ik[1], (float)ik[2], (float)ik[3]);
        *(float4*)&out[NT * TOPK + token * TOPK + 4] = make_float4((float)ik[4], (float)ik[5], (float)ik[6], (float)ik[7]);
    }
}

// ---------------- refine: exact fp32 recompute for near-tie tokens ----------------
__global__ void refine_kernel(const float* __restrict__ x,
                              const float* __restrict__ w,
                              const float* __restrict__ gate_b,
                              float* __restrict__ out)
{
    __shared__ float xs[DIM];
    __shared__ float part[NE][4];
    __shared__ float sc[NE];
    int n = g_nflag;
    if (n > 8192) n = 8192;
    for (int i = blockIdx.x; i < n; i += gridDim.x) {
        const int token = g_flags[i];
        __syncthreads();
        for (int d = threadIdx.x; d < DIM; d += 256) xs[d] = x[(long)token * DIM + d];
        __syncthreads();
        {
            const int e = threadIdx.x >> 2, q = threadIdx.x & 3;
            const float* wr = w + (long)e * DIM + q * 512;
            const float* xr = xs + q * 512;
            float s0 = 0.f, s1 = 0.f, s2 = 0.f, s3 = 0.f;
#pragma unroll 8
            for (int d = 0; d < 512; d += 4) {
                s0 = fmaf(xr[d], wr[d], s0);
                s1 = fmaf(xr[d + 1], wr[d + 1], s1);
                s2 = fmaf(xr[d + 2], wr[d + 2], s2);
                s3 = fmaf(xr[d + 3], wr[d + 3], s3);
            }
            part[e][q] = (s0 + s1) + (s2 + s3);
        }
        __syncthreads();
        if (threadIdx.x < NE) {
            float l = (part[threadIdx.x][0] + part[threadIdx.x][1]) +
                      (part[threadIdx.x][2] + part[threadIdx.x][3]);
            float v = 1.f / (1.f + expf(-l)) + gate_b[threadIdx.x];
            sc[threadIdx.x] = v;
            out[2L * NT * TOPK + (long)token * NE + threadIdx.x] = v;
        }
        __syncthreads();
        if (threadIdx.x == 0) {
            unsigned m0 = 0, m1 = 0;
            float wk[TOPK];
            int ik[TOPK];
            float sum = 0.f;
            for (int k = 0; k < TOPK; k++) {
                float best = -1e30f;
                int bi = 0;
                for (int e = 0; e < NE; e++) {
                    unsigned bit = (e < 32) ? (m0 >> e) : (m1 >> (e - 32));
                    if (((bit & 1u) == 0u) && (sc[e] > best)) { best = sc[e]; bi = e; }
                }
                if (bi < 32) m0 |= (1u << bi); else m1 |= (1u << (bi - 32));
                wk[k] = best; ik[k] = bi; sum += best;
            }
            float inv = 1.f / sum;
            for (int k = 0; k < TOPK; k++) {
                out[(long)token * TOPK + k] = wk[k] * inv;
                out[NT * TOPK + (long)token * TOPK + k] = (float)ik[k];
            }
        }
        __syncthreads();
    }
}

// ---------------- host ----------------
typedef CUresult (*EncodeFn)(CUtensorMap*, CUtensorMapDataType, cuuint32_t, void*,
                             const cuuint64_t*, const cuuint64_t*, const cuuint32_t*,
                             const cuuint32_t*, CUtensorMapInterleave, CUtensorMapSwizzle,
                             CUtensorMapL2promotion, CUtensorMapFloatOOBfill);

static EncodeFn get_encode_fn() {
    static EncodeFn fn = nullptr;
    if (!fn) {
        void* p = nullptr;
        cudaDriverEntryPointQueryResult qr;
        cudaGetDriverEntryPoint("cuTensorMapEncodeTiled", &p, cudaEnableDefault, &qr);
        fn = (EncodeFn)p;
    }
    return fn;
}

extern "C" void kernel_launch(void* const* d_in, const int* in_sizes, int n_in,
                              void* d_out, int out_size) {
    const float* x  = (const float*)d_in[0];
    const float* w  = (const float*)d_in[1];
    const float* gb = (const float*)d_in[2];
    float* out = (float*)d_out;

    prep_kernel<<<(NE * DIM) / 256, 256>>>(w);

    void* whp = nullptr;
    cudaGetSymbolAddress(&whp, g_wh);

    EncodeFn enc = get_encode_fn();
    CUtensorMap tmx, tmw;
    {
        cuuint64_t dims[2]    = {DIM, NT};
        cuuint64_t strides[1] = {DIM * sizeof(float)};
        cuuint32_t box[2]     = {KC, TILE_M};
        cuuint32_t es[2]      = {1, 1};
        enc(&tmx, CU_TENSOR_MAP_DATA_TYPE_FLOAT32, 2, (void*)x,
            dims, strides, box, es,
            CU_TENSOR_MAP_INTERLEAVE_NONE, CU_TENSOR_MAP_SWIZZLE_NONE,
            CU_TENSOR_MAP_L2_PROMOTION_L2_128B, CU_TENSOR_MAP_FLOAT_OOB_FILL_NONE);
    }
    {
        cuuint64_t dims[2]    = {DIM, 2 * NE};
        cuuint64_t strides[1] = {DIM * sizeof(__half)};
        cuuint32_t box[2]     = {KC, 2 * NE};
        cuuint32_t es[2]      = {1, 1};
        enc(&tmw, CU_TENSOR_MAP_DATA_TYPE_FLOAT16, 2, whp,
            dims, strides, box, es,
            CU_TENSOR_MAP_INTERLEAVE_NONE, CU_TENSOR_MAP_SWIZZLE_128B,
            CU_TENSOR_MAP_L2_PROMOTION_L2_128B, CU_TENSOR_MAP_FLOAT_OOB_FILL_NONE);
    }

    cudaFuncSetAttribute(gate_kernel, cudaFuncAttributeMaxDynamicSharedMemorySize, SMEM_TOTAL);
    gate_kernel<<<NT / TILE_M, THREADS, SMEM_TOTAL>>>(tmx, tmw, gb, out);
    refine_kernel<<<2048, 256>>>(x, w, gb, out);
}

// round 12
// speedup vs baseline: 3.0848x; 1.0385x over previous
#include <cuda_runtime.h>
#include <cuda.h>
#include <cuda_fp16.h>
#include <math.h>
#include <stdint.h>

// ---------------- problem constants ----------------
#define NT      16384
#define DIM     2048
#define NE      64
#define TOPK    8
#define TILE_M  64
#define KC      64
#define NCHUNK  (DIM / KC)     // 32
#define THREADS 256

// ---------------- smem layout (dynamic, bytes) ----------------
#define X_STAGE  16384                         // 64 x 64 fp32
#define W_STAGE  16384                         // 128 rows (w0|w1) x 64 fp16
#define XH_STAGE 8192                          // 64 x 64 fp16
#define OFF_MBAR 0
#define OFF_GB   64
#define OFF_X    1024
#define OFF_W    (OFF_X + 2 * X_STAGE)         // 33792
#define OFF_XH0  (OFF_W + 2 * W_STAGE)         // 66560
#define OFF_XH1  (OFF_XH0 + 2 * XH_STAGE)      // 82944
#define SMEM_TOTAL (OFF_XH1 + 2 * XH_STAGE)    // 99328  -> 2 CTAs/SM
#define TX_BYTES (X_STAGE + W_STAGE)

// split router weights: rows 0..63 = h0(w[e]), rows 64..127 = h1 residual
__device__ __align__(1024) __half g_wh[2 * NE * DIM];
__device__ int g_nflag;
__device__ int g_flags[8192];

// ---------------- helpers ----------------
__device__ __forceinline__ uint32_t smem_u32(const void* p) {
    uint32_t a;
    asm("{ .reg .u64 t; cvta.to.shared.u64 t, %1; cvt.u32.u64 %0, t; }" : "=r"(a) : "l"(p));
    return a;
}

#define MBAR_INIT(addr, cnt) \
    asm volatile("mbarrier.init.shared.b64 [%0], %1;" :: "r"(addr), "r"((uint32_t)(cnt)) : "memory")
#define MBAR_EXPECT_TX(addr, bytes) \
    asm volatile("mbarrier.arrive.expect_tx.shared.b64 _, [%0], %1;" :: "r"(addr), "r"((uint32_t)(bytes)) : "memory")

#define MBAR_WAIT(addr, parity) do {                                           \
    uint32_t _m = (addr); uint32_t _p = (parity); uint32_t _d;                 \
    asm volatile("{\n\t.reg .pred p;\n\t"                                      \
        "mbarrier.try_wait.parity.acquire.cta.shared::cta.b64 p, [%1], %2;\n\t"\
        "selp.b32 %0, 1, 0, p;\n\t}"                                           \
        : "=r"(_d) : "r"(_m), "r"(_p) : "memory");                             \
    if (!_d) {                                                                 \
        asm volatile("{\n\t.reg .pred P1;\n\t"                                 \
            "WL_%=:\n\t"                                                       \
            "mbarrier.try_wait.parity.acquire.cta.shared::cta.b64 P1, [%0], %1, 0x989680;\n\t" \
            "@P1 bra.uni WD_%=;\n\t"                                           \
            "bra.uni WL_%=;\n\t"                                               \
            "WD_%=:\n\t}" :: "r"(_m), "r"(_p) : "memory");                     \
    }                                                                          \
} while (0)

__device__ __forceinline__ void tma_2d(uint32_t dst, const CUtensorMap* map,
                                       int32_t cx, int32_t cy, uint32_t mbar) {
    asm volatile(
        "cp.async.bulk.tensor.2d.shared::cta.global.tile.mbarrier::complete_tx::bytes "
        "[%0], [%1, {%2, %3}], [%4];"
        :: "r"(dst), "l"(map), "r"(cx), "r"(cy), "r"(mbar) : "memory");
}

#define LDSM4(r, addr)                                                         \
    asm volatile("ldmatrix.sync.aligned.m8n8.x4.shared.b16 {%0,%1,%2,%3}, [%4];" \
        : "=r"((r)[0]), "=r"((r)[1]), "=r"((r)[2]), "=r"((r)[3]) : "r"(addr))

#define MMA16816(c, a, b0, b1)                                                 \
    asm volatile("mma.sync.aligned.m16n8k16.row.col.f32.f16.f16.f32 "          \
        "{%0,%1,%2,%3}, {%4,%5,%6,%7}, {%8,%9}, {%0,%1,%2,%3};"                \
        : "+f"((c)[0]), "+f"((c)[1]), "+f"((c)[2]), "+f"((c)[3])               \
        : "r"((a)[0]), "r"((a)[1]), "r"((a)[2]), "r"((a)[3]), "r"(b0), "r"(b1))

// SW128: 16B group g in 128B row r -> g ^ (r&7)
__device__ __forceinline__ uint32_t SWZ(int r, int k) {
    return (uint32_t)(r * 128 + ((((k) >> 3) ^ (r & 7)) << 4));
}

// ---------------- prep: split w to fp16 pairs; reset flag count ----------------
__global__ void prep_kernel(const float* __restrict__ w) {
    int i = blockIdx.x * 256 + threadIdx.x;    // 0 .. NE*DIM-1
    if (i == 0) g_nflag = 0;
    float a = w[i];
    __half h0 = __float2half_rn(a);
    float r = a - __half2float(h0);
    __half h1 = __float2half_rn(r);
    int e = i >> 11, d = i & 2047;
    g_wh[e * DIM + d] = h0;
    g_wh[(NE + e) * DIM + d] = h1;
}

// ---------------- main gate kernel (fp16 3-term split, 2 CTAs/SM) ----------------
__global__ __launch_bounds__(THREADS, 2) void gate_kernel(
    const __grid_constant__ CUtensorMap tmx,
    const __grid_constant__ CUtensorMap tmw,
    const float* __restrict__ gate_b,
    float* __restrict__ out)
{
    extern __shared__ __align__(1024) char smem[];
    const uint32_t sb = smem_u32(smem);
    const int tid = threadIdx.x;
    const int lane = tid & 31;
    const int wid = tid >> 5;
    const int tok0 = blockIdx.x * TILE_M;

    if (tid == 0) {
        MBAR_INIT(sb + OFF_MBAR + 0, 1);
        MBAR_INIT(sb + OFF_MBAR + 8, 1);
    }
    if (tid < NE) ((float*)(smem + OFF_GB))[tid] = gate_b[tid];
    __syncthreads();

    if (tid == 0) {
#pragma unroll
        for (int c = 0; c < 2; c++) {
            MBAR_EXPECT_TX(sb + OFF_MBAR + c * 8, TX_BYTES);
            tma_2d(sb + OFF_X + c * X_STAGE, &tmx, c * KC, tok0, sb + OFF_MBAR + c * 8);
            tma_2d(sb + OFF_W + c * W_STAGE, &tmw, c * KC, 0, sb + OFF_MBAR + c * 8);
        }
    }

    // warp tile: 16 tokens x 32 experts; 4 independent acc chains
    float acc[4][4];
#pragma unroll
    for (int nt = 0; nt < 4; nt++)
#pragma unroll
        for (int j = 0; j < 4; j++) acc[nt][j] = 0.f;

    const int wm = wid & 3, wn = wid >> 2;
    const int tm0 = wm * 16, en0 = wn * 32;
    const int ar = (lane & 7) + ((lane & 8) ? 8 : 0);
    const int ak = (lane & 16) ? 8 : 0;
    const int br = (lane & 7) + ((lane & 16) ? 8 : 0);
    const int bk = (lane & 8) ? 8 : 0;

    for (int c = 0; c < NCHUNK; c++) {
        const int s = c & 1, ph = (c >> 1) & 1;
        MBAR_WAIT(sb + OFF_MBAR + s * 8, ph);

        // ---- convert x fp32 -> (h0, h1) fp16 tiles with SW128 ----
        {
            const char* xsrc = smem + OFF_X + s * X_STAGE;
            char* d0 = smem + OFF_XH0 + s * XH_STAGE;
            char* d1 = smem + OFF_XH1 + s * XH_STAGE;
#pragma unroll
            for (int i = 0; i < 8; i++) {
                int p = tid + i * THREADS;                 // pair index 0..2047
                float2 v = *(const float2*)(xsrc + p * 8);
                __half2 h0 = __float22half2_rn(v);
                float2 bl = __half22float2(h0);
                __half2 h1 = __float22half2_rn(make_float2(v.x - bl.x, v.y - bl.y));
                int row = p >> 5, pc = p & 31;
                uint32_t off = (uint32_t)(row * 128 + ((((pc >> 2)) ^ (row & 7)) << 4) + (pc & 3) * 4);
                *(__half2*)(d0 + off) = h0;
                *(__half2*)(d1 + off) = h1;
            }
        }
        __syncthreads();

        // ---- MMA: 3 terms (x0w0, x0w1, x1w0) over this K=64 chunk ----
        {
            const uint32_t xh0b = sb + OFF_XH0 + s * XH_STAGE;
            const uint32_t xh1b = sb + OFF_XH1 + s * XH_STAGE;
            const uint32_t wb = sb + OFF_W + s * W_STAGE;
#pragma unroll
            for (int ks = 0; ks < 4; ks++) {
                const int kk = ks * 16;
                uint32_t a0[4], a1[4];
                LDSM4(a0, xh0b + SWZ(tm0 + ar, kk + ak));
                LDSM4(a1, xh1b + SWZ(tm0 + ar, kk + ak));
                uint32_t b0[8], b1[8];
                LDSM4(b0 + 0, wb + SWZ(en0 + br, kk + bk));
                LDSM4(b0 + 4, wb + SWZ(en0 + 16 + br, kk + bk));
                LDSM4(b1 + 0, wb + SWZ(64 + en0 + br, kk + bk));
                LDSM4(b1 + 4, wb + SWZ(64 + en0 + 16 + br, kk + bk));
                // pass 1: x0*w0 across 4 independent accs
#pragma unroll
                for (int nt = 0; nt < 4; nt++)
                    MMA16816(acc[nt], a0, b0[2 * nt], b0[2 * nt + 1]);
                // pass 2: x0*w1
#pragma unroll
                for (int nt = 0; nt < 4; nt++)
                    MMA16816(acc[nt], a0, b1[2 * nt], b1[2 * nt + 1]);
                // pass 3: x1*w0
#pragma unroll
                for (int nt = 0; nt < 4; nt++)
                    MMA16816(acc[nt], a1, b0[2 * nt], b0[2 * nt + 1]);
            }
        }
        __syncthreads();

        if (tid == 0 && c + 2 < NCHUNK) {
            MBAR_EXPECT_TX(sb + OFF_MBAR + s * 8, TX_BYTES);
            tma_2d(sb + OFF_X + s * X_STAGE, &tmx, (c + 2) * KC, tok0, sb + OFF_MBAR + s * 8);
            tma_2d(sb + OFF_W + s * W_STAGE, &tmw, (c + 2) * KC, 0, sb + OFF_MBAR + s * 8);
        }
    }

    // ---- epilogue: logits -> smem, then per-token sigmoid + top-8 ----
    float* sc = (float*)(smem + OFF_X);   // [64][68]
    {
        const int g = lane >> 2, q = lane & 3;
#pragma unroll
        for (int nt = 0; nt < 4; nt++) {
            int t0 = tm0 + g;
            int e0 = en0 + nt * 8 + q * 2;
            sc[t0 * 68 + e0] = acc[nt][0];
            sc[t0 * 68 + e0 + 1] = acc[nt][1];
            sc[(t0 + 8) * 68 + e0] = acc[nt][2];
            sc[(t0 + 8) * 68 + e0 + 1] = acc[nt][3];
        }
    }
    __syncthreads();

    if (tid < TILE_M) {
        const long token = tok0 + tid;
        const float* gb = (const float*)(smem + OFF_GB);
        float s[NE];
#pragma unroll
        for (int e = 0; e < NE; e++)
            s[e] = 1.f / (1.f + expf(-sc[tid * 68 + e])) + gb[e];

        float* so = out + 2L * NT * TOPK + token * NE;
#pragma unroll
        for (int i = 0; i < 16; i++)
            *(float4*)&so[4 * i] = make_float4(s[4 * i], s[4 * i + 1], s[4 * i + 2], s[4 * i + 3]);

        // top-8, strict > keeps lowest index on ties
        unsigned m0 = 0, m1 = 0;
        float wk[TOPK];
        int ik[TOPK];
        float sum = 0.f;
#pragma unroll 1
        for (int k = 0; k < TOPK; k++) {
            float best = -1e30f;
            int bi = 0;
#pragma unroll
            for (int e = 0; e < NE; e++) {
                unsigned bit = (e < 32) ? (m0 >> e) : (m1 >> (e - 32));
                if (((bit & 1u) == 0u) && (s[e] > best)) { best = s[e]; bi = e; }
            }
            if (bi < 32) m0 |= (1u << bi); else m1 |= (1u << (bi - 32));
            wk[k] = best; ik[k] = bi; sum += best;
        }
        // near-tie detection (threshold 4e-6: >10x the measured 3-term error)
        float v9 = -1e30f;
#pragma unroll
        for (int e = 0; e < NE; e++) {
            unsigned bit = (e < 32) ? (m0 >> e) : (m1 >> (e - 32));
            if (((bit & 1u) == 0u) && (s[e] > v9)) v9 = s[e];
        }
        float mingap = wk[TOPK - 1] - v9;
#pragma unroll
        for (int k = 0; k < TOPK - 1; k++) {
            float gdiff = wk[k] - wk[k + 1];
            if (gdiff < mingap) mingap = gdiff;
        }
        if (mingap < 4e-6f) {
            int ix = atomicAdd(&g_nflag, 1);
            if (ix < 8192) g_flags[ix] = (int)token;
        }

        float inv = 1.f / sum;
        *(float4*)&out[token * TOPK] = make_float4(wk[0] * inv, wk[1] * inv, wk[2] * inv, wk[3] * inv);
        *(float4*)&out[token * TOPK + 4] = make_float4(wk[4] * inv, wk[5] * inv, wk[6] * inv, wk[7] * inv);
        *(float4*)&out[NT * TOPK + token * TOPK] = make_float4((float)ik[0], (float)ik[1], (float)ik[2], (float)ik[3]);
        *(float4*)&out[NT * TOPK + token * TOPK + 4] = make_float4((float)ik[4], (float)ik[5], (float)ik[6], (float)ik[7]);
    }
}

// ---------------- refine: exact fp32 recompute for near-tie tokens ----------------
__global__ void refine_kernel(const float* __restrict__ x,
                              const float* __restrict__ w,
                              const float* __restrict__ gate_b,
                              float* __restrict__ out)
{
    __shared__ float xs[DIM];
    __shared__ float part[NE][4];
    __shared__ float sc[NE];
    int n = g_nflag;
    if (n > 8192) n = 8192;
    for (int i = blockIdx.x; i < n; i += gridDim.x) {
        const int token = g_flags[i];
        __syncthreads();
        for (int d = threadIdx.x; d < DIM; d += 256) xs[d] = x[(long)token * DIM + d];
        __syncthreads();
        {
            const int e = threadIdx.x >> 2, q = threadIdx.x & 3;
            const float* wr = w + (long)e * DIM + q * 512;
            const float* xr = xs + q * 512;
            float s0 = 0.f, s1 = 0.f, s2 = 0.f, s3 = 0.f;
#pragma unroll 8
            for (int d = 0; d < 512; d += 4) {
                s0 = fmaf(xr[d], wr[d], s0);
                s1 = fmaf(xr[d + 1], wr[d + 1], s1);
                s2 = fmaf(xr[d + 2], wr[d + 2], s2);
                s3 = fmaf(xr[d + 3], wr[d + 3], s3);
            }
            part[e][q] = (s0 + s1) + (s2 + s3);
        }
        __syncthreads();
        if (threadIdx.x < NE) {
            float l = (part[threadIdx.x][0] + part[threadIdx.x][1]) +
                      (part[threadIdx.x][2] + part[threadIdx.x][3]);
            float v = 1.f / (1.f + expf(-l)) + gate_b[threadIdx.x];
            sc[threadIdx.x] = v;
            out[2L * NT * TOPK + (long)token * NE + threadIdx.x] = v;
        }
        __syncthreads();
        if (threadIdx.x == 0) {
            unsigned m0 = 0, m1 = 0;
            float wk[TOPK];
            int ik[TOPK];
            float sum = 0.f;
            for (int k = 0; k < TOPK; k++) {
                float best = -1e30f;
                int bi = 0;
                for (int e = 0; e < NE; e++) {
                    unsigned bit = (e < 32) ? (m0 >> e) : (m1 >> (e - 32));
                    if (((bit & 1u) == 0u) && (sc[e] > best)) { best = sc[e]; bi = e; }
                }
                if (bi < 32) m0 |= (1u << bi); else m1 |= (1u << (bi - 32));
                wk[k] = best; ik[k] = bi; sum += best;
            }
            float inv = 1.f / sum;
            for (int k = 0; k < TOPK; k++) {
                out[(long)token * TOPK + k] = wk[k] * inv;
                out[NT * TOPK + (long)token * TOPK + k] = (float)ik[k];
            }
        }
        __syncthreads();
    }
}

// ---------------- host ----------------
typedef CUresult (*EncodeFn)(CUtensorMap*, CUtensorMapDataType, cuuint32_t, void*,
                             const cuuint64_t*, const cuuint64_t*, const cuuint32_t*,
                             const cuuint32_t*, CUtensorMapInterleave, CUtensorMapSwizzle,
                             CUtensorMapL2promotion, CUtensorMapFloatOOBfill);

static EncodeFn get_encode_fn() {
    static EncodeFn fn = nullptr;
    if (!fn) {
        void* p = nullptr;
        cudaDriverEntryPointQueryResult qr;
        cudaGetDriverEntryPoint("cuTensorMapEncodeTiled", &p, cudaEnableDefault, &qr);
        fn = (EncodeFn)p;
    }
    return fn;
}

extern "C" void kernel_launch(void* const* d_in, const int* in_sizes, int n_in,
                              void* d_out, int out_size) {
    const float* x  = (const float*)d_in[0];
    const float* w  = (const float*)d_in[1];
    const float* gb = (const float*)d_in[2];
    float* out = (float*)d_out;

    prep_kernel<<<(NE * DIM) / 256, 256>>>(w);

    void* whp = nullptr;
    cudaGetSymbolAddress(&whp, g_wh);

    EncodeFn enc = get_encode_fn();
    CUtensorMap tmx, tmw;
    {
        cuuint64_t dims[2]    = {DIM, NT};
        cuuint64_t strides[1] = {DIM * sizeof(float)};
        cuuint32_t box[2]     = {KC, TILE_M};
        cuuint32_t es[2]      = {1, 1};
        enc(&tmx, CU_TENSOR_MAP_DATA_TYPE_FLOAT32, 2, (void*)x,
            dims, strides, box, es,
            CU_TENSOR_MAP_INTERLEAVE_NONE, CU_TENSOR_MAP_SWIZZLE_NONE,
            CU_TENSOR_MAP_L2_PROMOTION_L2_128B, CU_TENSOR_MAP_FLOAT_OOB_FILL_NONE);
    }
    {
        cuuint64_t dims[2]    = {DIM, 2 * NE};
        cuuint64_t strides[1] = {DIM * sizeof(__half)};
        cuuint32_t box[2]     = {KC, 2 * NE};
        cuuint32_t es[2]      = {1, 1};
        enc(&tmw, CU_TENSOR_MAP_DATA_TYPE_FLOAT16, 2, whp,
            dims, strides, box, es,
            CU_TENSOR_MAP_INTERLEAVE_NONE, CU_TENSOR_MAP_SWIZZLE_128B,
            CU_TENSOR_MAP_L2_PROMOTION_L2_128B, CU_TENSOR_MAP_FLOAT_OOB_FILL_NONE);
    }

    cudaFuncSetAttribute(gate_kernel, cudaFuncAttributeMaxDynamicSharedMemorySize, SMEM_TOTAL);
    gate_kernel<<<NT / TILE_M, THREADS, SMEM_TOTAL>>>(tmx, tmw, gb, out);
    refine_kernel<<<2048, 256>>>(x, w, gb, out);
}